// round 15
// baseline (speedup 1.0000x reference)
#include <cuda_runtime.h>

// Bilinear grid-sample, v11: binning with self-contained packed payload,
// 17-bit tile-relative fixed-point coords (v10 failed accuracy at 12 bits).
//
// Payload word (8B): pix:21 | xq:21 | yq:21, where xq = trunc((x - tx)*2^17).
// All decode arithmetic exact; only error is 2^-17 truncation (~7.6e-6 coord,
// ~1e-4 output rel_err). Weights in fraction form == reference formula for
// x<511; x==511.0 boundary handled with an explicit zero-scale to match the
// reference's all-zero-weight behavior.
//
// K1: 512 CTAs; smem hist + packed smem lists; masked coalesced flush.
// K2: 8192 CTAs, 256 thr, 0.3KB smem, 5 CTAs/SM; branch-free, no dependent
//     loads; bin's 37KB image region dedups in L1.

#define B_ 8
#define H_ 512
#define W_ 512
#define NPIX (B_ * H_ * W_)
#define NPAIR (NPIX / 2)

#define NBINS 8192                 // 8 batches * 32x32 tiles of 16x16 px
#define NCHUNK 64
#define CAP 16                     // lambda=4
#define SLOTS (NCHUNK * CAP)       // 1024

#define NCTA1 512
#define PAIRS1 (NPAIR / NCTA1)     // 2048 pairs

#define SMEM_K1 (1024 * 4 + 1024 * CAP * 8)   // 135,168 B
#define OVF_CAP 8192
#define K2T 256

#define QSF  131072.0f             // 2^17
#define IQF  (1.0f / 131072.0f)
#define QMASK 0x1FFFFu

__device__ unsigned g_cnt[NBINS * NCHUNK];         // [bin][chunk]
__device__ uint2    g_pay[(size_t)NBINS * SLOTS];  // 67MB packed payload
__device__ unsigned g_ovf_cnt;                     // zero-init; K2 CTA0 resets
__device__ unsigned g_ovf[OVF_CAP];
__device__ const float2* g_grid2_dev;

// quantize absolute coords -> (xq, yq) relative to tile origin (exact except
// the final 2^-17 truncation)
__device__ __forceinline__ void quantize(float x, float y,
                                         int& tx, int& ty,
                                         unsigned& xq, unsigned& yq)
{
    int x0 = (int)floorf(x);
    int y0 = (int)floorf(y);
    tx = (x0 >> 4) << 4;
    ty = (y0 >> 4) << 4;
    xq = (unsigned)((x - (float)tx) * QSF);   // trunc; < 2^21
    yq = (unsigned)((y - (float)ty) * QSF);
}

// decode + reference-exact weights (fraction form; boundary-zero at 511)
__device__ __forceinline__ void decode_weights(
    unsigned xq, unsigned yq, int tx, int ty,
    int& x0, int& y0, int& x1, int& y1,
    float& wa, float& wb, float& wc, float& wd)
{
    x0 = tx + (int)(xq >> 17);
    y0 = ty + (int)(yq >> 17);
    x1 = min(x0 + 1, W_ - 1);
    y1 = min(y0 + 1, H_ - 1);
    float fx = (float)(xq & QMASK) * IQF;
    float fy = (float)(yq & QMASK) * IQF;
    float sx = (x0 == W_ - 1) ? 0.0f : 1.0f;   // x==511.0 -> all weights 0
    float sy = (y0 == H_ - 1) ? 0.0f : 1.0f;
    float gx0 = fx * sx, gx1 = (1.0f - fx) * sx;
    float gy0 = fy * sy, gy1 = (1.0f - fy) * sy;
    wa = gx1 * gy1;   // (x1-x)(y1-y)
    wb = gx1 * gy0;   // (x1-x)(y-y0)
    wc = gx0 * gy1;   // (x-x0)(y1-y)
    wd = gx0 * gy0;   // (x-x0)(y-y0)
}

// ------------------------------------------------------------ K1: hist + scatter
__global__ __launch_bounds__(512)
void hist_kernel(const float4* __restrict__ grid4)
{
    extern __shared__ unsigned sm[];
    unsigned* hist = sm;                       // 1024
    uint2*    lists = (uint2*)(sm + 1024);     // 1024 * CAP

    int cta = blockIdx.x, tid = threadIdx.x;
    hist[tid] = 0;
    hist[tid + 512] = 0;
    __syncthreads();

    unsigned pairBase = (unsigned)cta * PAIRS1;
    unsigned batch = (unsigned)cta >> 6;       // 64 CTAs per batch
    unsigned chunk = (unsigned)cta & 63u;

    float4 gs[4];
    #pragma unroll
    for (int c = 0; c < 4; c++)
        gs[c] = __ldcs(&grid4[pairBase + c * 512 + tid]);

    #pragma unroll
    for (int c = 0; c < 4; c++) {
        unsigned pr = pairBase + c * 512 + tid;
        #pragma unroll
        for (int h = 0; h < 2; h++) {
            float gx = h ? gs[c].z : gs[c].x;
            float gy = h ? gs[c].w : gs[c].y;
            unsigned pix = pr * 2u + h;
            float x = fminf(fmaxf(fmaf(gx, 255.5f, 255.5f), 0.0f), 511.0f);
            float y = fminf(fmaxf(fmaf(gy, 255.5f, 255.5f), 0.0f), 511.0f);
            int tx, ty; unsigned xq, yq;
            quantize(x, y, tx, ty, xq, yq);
            unsigned lb = ((unsigned)(ty >> 4) << 5) | (unsigned)(tx >> 4);
            unsigned rank = atomicAdd(&hist[lb], 1u);
            if (rank < CAP) {
                unsigned long long v = (unsigned long long)pix
                                     | ((unsigned long long)xq << 21)
                                     | ((unsigned long long)yq << 42);
                lists[lb * CAP + rank] = make_uint2((unsigned)v, (unsigned)(v >> 32));
            } else {
                unsigned o = atomicAdd(&g_ovf_cnt, 1u);
                if (o < OVF_CAP) g_ovf[o] = pix;
            }
        }
    }
    __syncthreads();

    // masked coalesced flush of packed lists
    #pragma unroll
    for (int k = 0; k < (1024 * CAP) / 512; k++) {
        int i = tid + k * 512;
        unsigned lb = (unsigned)i >> 4;
        unsigned w  = (unsigned)i & 15u;
        if (w < min(hist[lb], (unsigned)CAP))
            g_pay[((size_t)((batch << 10) | lb) << 10) + (chunk << 4) + w] = lists[i];
    }
    g_cnt[(((batch << 10) | (unsigned)tid) << 6) + chunk] = hist[tid];
    g_cnt[(((batch << 10) | (unsigned)(tid + 512)) << 6) + chunk] = hist[tid + 512];
}

// ------------------------------------------------------------ K2: direct sampling
__global__ __launch_bounds__(K2T, 5)
void sample_kernel(const float4* __restrict__ img4,
                   float4* __restrict__ out4)
{
    __shared__ unsigned cnt_s[NCHUNK];
    int bid = blockIdx.x, tid = threadIdx.x;
    unsigned ibase = ((unsigned)bid >> 10) << 18;
    int lbq = bid & 1023;
    int ty = ((lbq >> 5) << 4);
    int tx = ((lbq & 31) << 4);

    if (tid < NCHUNK)
        cnt_s[tid] = min(g_cnt[((unsigned)bid << 6) + tid], (unsigned)CAP);
    __syncthreads();

    const uint2* pay = &g_pay[(size_t)bid << 10];
    int g = tid >> 3, cb = tid & 7;

    for (int s1 = g; s1 < SLOTS; s1 += 64) {
        int s2 = s1 + 32;
        bool v1 = ((unsigned)(s1 & 15) < cnt_s[s1 >> 4]);
        bool v2 = ((unsigned)(s2 & 15) < cnt_s[s2 >> 4]);

        uint2 p1 = __ldg(&pay[s1]);
        uint2 p2 = __ldg(&pay[s2]);
        unsigned long long w1 = (unsigned long long)p1.x | ((unsigned long long)p1.y << 32);
        unsigned long long w2 = (unsigned long long)p2.x | ((unsigned long long)p2.y << 32);
        if (!v1) w1 = 0;   // decodes to pix 0 / tile origin (hot line)
        if (!v2) w2 = 0;

        unsigned pix1 = (unsigned)(w1 & 0x1FFFFFu);
        unsigned pix2 = (unsigned)(w2 & 0x1FFFFFu);
        unsigned xq1 = (unsigned)(w1 >> 21) & 0x1FFFFFu;
        unsigned yq1 = (unsigned)(w1 >> 42) & 0x1FFFFFu;
        unsigned xq2 = (unsigned)(w2 >> 21) & 0x1FFFFFu;
        unsigned yq2 = (unsigned)(w2 >> 42) & 0x1FFFFFu;

        int ax0, ay0, ax1, ay1, bx0, by0, bx1, by1;
        float wa1, wb1, wc1, wd1, wa2, wb2, wc2, wd2;
        int tx1v = v1 ? tx : 0, ty1v = v1 ? ty : 0;   // invalid -> origin
        int tx2v = v2 ? tx : 0, ty2v = v2 ? ty : 0;
        decode_weights(xq1, yq1, tx1v, ty1v, ax0, ay0, ax1, ay1, wa1, wb1, wc1, wd1);
        decode_weights(xq2, yq2, tx2v, ty2v, bx0, by0, bx1, by1, wa2, wb2, wc2, wd2);

        unsigned ar0 = ibase + ((unsigned)ay0 << 9);
        unsigned ar1 = ibase + ((unsigned)ay1 << 9);
        unsigned br0 = ibase + ((unsigned)by0 << 9);
        unsigned br1 = ibase + ((unsigned)by1 << 9);

        float4 Ia1 = __ldg(&img4[((ar0 + ax0) << 3) + cb]);
        float4 Ib1 = __ldg(&img4[((ar1 + ax0) << 3) + cb]);
        float4 Ic1 = __ldg(&img4[((ar0 + ax1) << 3) + cb]);
        float4 Id1 = __ldg(&img4[((ar1 + ax1) << 3) + cb]);
        float4 Ia2 = __ldg(&img4[((br0 + bx0) << 3) + cb]);
        float4 Ib2 = __ldg(&img4[((br1 + bx0) << 3) + cb]);
        float4 Ic2 = __ldg(&img4[((br0 + bx1) << 3) + cb]);
        float4 Id2 = __ldg(&img4[((br1 + bx1) << 3) + cb]);

        if (v1) {
            float4 o;
            o.x = fmaf(wa1, Ia1.x, fmaf(wb1, Ib1.x, fmaf(wc1, Ic1.x, wd1 * Id1.x)));
            o.y = fmaf(wa1, Ia1.y, fmaf(wb1, Ib1.y, fmaf(wc1, Ic1.y, wd1 * Id1.y)));
            o.z = fmaf(wa1, Ia1.z, fmaf(wb1, Ib1.z, fmaf(wc1, Ic1.z, wd1 * Id1.z)));
            o.w = fmaf(wa1, Ia1.w, fmaf(wb1, Ib1.w, fmaf(wc1, Ic1.w, wd1 * Id1.w)));
            __stcs(&out4[(pix1 << 3) + cb], o);
        }
        if (v2) {
            float4 o;
            o.x = fmaf(wa2, Ia2.x, fmaf(wb2, Ib2.x, fmaf(wc2, Ic2.x, wd2 * Id2.x)));
            o.y = fmaf(wa2, Ia2.y, fmaf(wb2, Ib2.y, fmaf(wc2, Ic2.y, wd2 * Id2.y)));
            o.z = fmaf(wa2, Ia2.z, fmaf(wb2, Ib2.z, fmaf(wc2, Ic2.z, wd2 * Id2.z)));
            o.w = fmaf(wa2, Ia2.w, fmaf(wb2, Ib2.w, fmaf(wc2, Ic2.w, wd2 * Id2.w)));
            __stcs(&out4[(pix2 << 3) + cb], o);
        }
    }

    // CTA 0: fixup for overflow px via the SAME quantize/decode path.
    if (bid == 0) {
        unsigned nf = g_ovf_cnt;
        if (nf > OVF_CAP) nf = OVF_CAP;
        for (unsigned i = tid; i < nf; i += K2T) {
            unsigned pix = g_ovf[i];
            float2 gg = __ldg(&g_grid2_dev[pix]);
            float x = fminf(fmaxf(fmaf(gg.x, 255.5f, 255.5f), 0.0f), 511.0f);
            float y = fminf(fmaxf(fmaf(gg.y, 255.5f, 255.5f), 0.0f), 511.0f);
            int ftx, fty; unsigned xq, yq;
            quantize(x, y, ftx, fty, xq, yq);
            int x0, y0, x1, y1;
            float wa, wb, wc, wd;
            decode_weights(xq, yq, ftx, fty, x0, y0, x1, y1, wa, wb, wc, wd);
            unsigned bb = (pix >> 18) << 18;
            const float4* pa = img4 + ((bb + ((unsigned)y0 << 9) + x0) << 3);
            const float4* pb = img4 + ((bb + ((unsigned)y1 << 9) + x0) << 3);
            const float4* pc = img4 + ((bb + ((unsigned)y0 << 9) + x1) << 3);
            const float4* pd = img4 + ((bb + ((unsigned)y1 << 9) + x1) << 3);
            float4* po = out4 + (pix << 3);
            for (int c = 0; c < 8; c++) {
                float4 Ia = pa[c], Ib = pb[c], Ic = pc[c], Id = pd[c];
                float4 o;
                o.x = fmaf(wa, Ia.x, fmaf(wb, Ib.x, fmaf(wc, Ic.x, wd * Id.x)));
                o.y = fmaf(wa, Ia.y, fmaf(wb, Ib.y, fmaf(wc, Ic.y, wd * Id.y)));
                o.z = fmaf(wa, Ia.z, fmaf(wb, Ib.z, fmaf(wc, Ic.z, wd * Id.z)));
                o.w = fmaf(wa, Ia.w, fmaf(wb, Ib.w, fmaf(wc, Ic.w, wd * Id.w)));
                po[c] = o;
            }
        }
        __syncthreads();
        if (tid == 0) g_ovf_cnt = 0;
    }
}

__global__ void set_grid_ptr(const float2* g) { g_grid2_dev = g; }

// ------------------------------------------------------------ launch
extern "C" void kernel_launch(void* const* d_in, const int* in_sizes, int n_in,
                              void* d_out, int out_size)
{
    const float4* img4  = (const float4*)d_in[0];
    const float4* grid4 = (const float4*)d_in[1];
    const float2* grid2 = (const float2*)d_in[1];
    float4* out4 = (float4*)d_out;

    cudaFuncSetAttribute(hist_kernel,
                         cudaFuncAttributeMaxDynamicSharedMemorySize, SMEM_K1);

    set_grid_ptr<<<1, 1>>>(grid2);
    hist_kernel<<<NCTA1, 512, SMEM_K1>>>(grid4);
    sample_kernel<<<NBINS, K2T>>>(img4, out4);
}

// round 16
// speedup vs baseline: 2.1061x; 2.1061x over previous
#include <cuda_runtime.h>

// Bilinear grid-sample — final: single-pass, 2 pixels/thread (proven R2 config).
//
// img  [B=8, H=512, W=512, C=32] f32   (pixel row = 128B, exactly one L2 line)
// grid [B, H, W, 2] f32 in [-1,1]
// out  [B, H, W, C] f32
//
// 8 threads per pixel (float4 channels), 2 adjacent pixels per thread:
// one float4 grid load serves both pixels, 8 independent 128B corner gathers
// in flight per thread. This kernel runs at the measured LTS achievable cap
// (~6300 B/cyc): 1.36GB L2 traffic / 112.7us = 12.1 TB/s. Ten binned/tiled
// variants (R3-R15) that cut gather traffic 4x never beat it — their DRAM
// utilization ceiling (~56%) ate the savings. __ldcs on grid keeps the
// once-read 17MB from displacing image lines in L2.

#define B_ 8
#define H_ 512
#define W_ 512
#define C_ 32
#define NPIX (B_ * H_ * W_)          // 2,097,152
#define NPAIR (NPIX / 2)             // 1,048,576
#define NTHREADS (NPAIR * 8)         // 8,388,608

__device__ __forceinline__ void pixel_setup(
    float gx, float gy, int bbase, int cb,
    unsigned& oa, unsigned& ob, unsigned& oc, unsigned& od,
    float& wa, float& wb, float& wc, float& wd)
{
    // unnormalize: 0.5*((g+1)*511) = g*255.5 + 255.5
    float x = fmaf(gx, 255.5f, 255.5f);
    float y = fmaf(gy, 255.5f, 255.5f);

    float xf = floorf(x);
    float yf = floorf(y);
    int x0 = (int)xf;
    int y0 = (int)yf;

    int x0c = min(max(x0, 0), W_ - 1);
    int x1c = min(max(x0 + 1, 0), W_ - 1);
    int y0c = min(max(y0, 0), H_ - 1);
    int y1c = min(max(y0 + 1, 0), H_ - 1);

    float dx0 = (float)x0c, dx1 = (float)x1c;
    float dy0 = (float)y0c, dy1 = (float)y1c;

    wa = (dx1 - x) * (dy1 - y);
    wb = (dx1 - x) * (y - dy0);
    wc = (x - dx0) * (dy1 - y);
    wd = (x - dx0) * (y - dy0);

    // byte offsets into img (max 2^28-1, fits unsigned)
    unsigned r0 = (unsigned)(bbase + (y0c << 9));   // row base in pixels
    unsigned r1 = (unsigned)(bbase + (y1c << 9));
    oa = ((((r0 + x0c) << 3) + cb) << 4);
    ob = ((((r1 + x0c) << 3) + cb) << 4);
    oc = ((((r0 + x1c) << 3) + cb) << 4);
    od = ((((r1 + x1c) << 3) + cb) << 4);
}

__global__ __launch_bounds__(128, 9)
void grid_sample_kernel(const char* __restrict__ img_bytes,
                        const float4* __restrict__ grid4,
                        float4* __restrict__ out4)
{
    int gtid = blockIdx.x * 128 + threadIdx.x;
    int pair = gtid >> 3;
    int cb   = gtid & 7;
    int pix0 = pair << 1;              // even pixel; pairs never straddle a batch
    int bbase = (pix0 >> 18) << 18;    // b * H * W

    float4 g = __ldcs(&grid4[pair]);   // (x0, y0, x1, y1) for pixels pix0, pix0+1

    unsigned oa0, ob0, oc0, od0, oa1, ob1, oc1, od1;
    float wa0, wb0, wc0, wd0, wa1, wb1, wc1, wd1;
    pixel_setup(g.x, g.y, bbase, cb, oa0, ob0, oc0, od0, wa0, wb0, wc0, wd0);
    pixel_setup(g.z, g.w, bbase, cb, oa1, ob1, oc1, od1, wa1, wb1, wc1, wd1);

    // Issue all 8 gathers before consuming any (MLP = 8 per thread).
    float4 Ia0 = __ldg((const float4*)(img_bytes + oa0));
    float4 Ib0 = __ldg((const float4*)(img_bytes + ob0));
    float4 Ic0 = __ldg((const float4*)(img_bytes + oc0));
    float4 Id0 = __ldg((const float4*)(img_bytes + od0));
    float4 Ia1 = __ldg((const float4*)(img_bytes + oa1));
    float4 Ib1 = __ldg((const float4*)(img_bytes + ob1));
    float4 Ic1 = __ldg((const float4*)(img_bytes + oc1));
    float4 Id1 = __ldg((const float4*)(img_bytes + od1));

    float4 o0;
    o0.x = fmaf(wa0, Ia0.x, fmaf(wb0, Ib0.x, fmaf(wc0, Ic0.x, wd0 * Id0.x)));
    o0.y = fmaf(wa0, Ia0.y, fmaf(wb0, Ib0.y, fmaf(wc0, Ic0.y, wd0 * Id0.y)));
    o0.z = fmaf(wa0, Ia0.z, fmaf(wb0, Ib0.z, fmaf(wc0, Ic0.z, wd0 * Id0.z)));
    o0.w = fmaf(wa0, Ia0.w, fmaf(wb0, Ib0.w, fmaf(wc0, Ic0.w, wd0 * Id0.w)));
    __stcs(&out4[((long)pix0 << 3) + cb], o0);

    float4 o1;
    o1.x = fmaf(wa1, Ia1.x, fmaf(wb1, Ib1.x, fmaf(wc1, Ic1.x, wd1 * Id1.x)));
    o1.y = fmaf(wa1, Ia1.y, fmaf(wb1, Ib1.y, fmaf(wc1, Ic1.y, wd1 * Id1.y)));
    o1.z = fmaf(wa1, Ia1.z, fmaf(wb1, Ib1.z, fmaf(wc1, Ic1.z, wd1 * Id1.z)));
    o1.w = fmaf(wa1, Ia1.w, fmaf(wb1, Ib1.w, fmaf(wc1, Ic1.w, wd1 * Id1.w)));
    __stcs(&out4[(((long)pix0 + 1) << 3) + cb], o1);
}

extern "C" void kernel_launch(void* const* d_in, const int* in_sizes, int n_in,
                              void* d_out, int out_size)
{
    const char*   img_bytes = (const char*)d_in[0];
    const float4* grid4     = (const float4*)d_in[1];
    float4* out4 = (float4*)d_out;

    const int threads = 128;
    const int blocks = NTHREADS / threads;  // 65536, exact
    grid_sample_kernel<<<blocks, threads>>>(img_bytes, grid4, out4);
}

// round 17
// speedup vs baseline: 2.4984x; 1.1863x over previous
#include <cuda_runtime.h>

// Bilinear grid-sample — FINAL: single-pass, 2 pixels/thread.
// Byte-exact revert to the proven 112.7us R2 kernel (__ldg on grid; R16's
// __ldcs variant measured 133.9us with ~17% more L2 traffic).
//
// img  [B=8, H=512, W=512, C=32] f32   (pixel row = 128B, exactly one L2 line)
// grid [B, H, W, 2] f32 in [-1,1]
// out  [B, H, W, C] f32
//
// 8 threads per pixel (float4 channels), 2 adjacent pixels per thread:
// one float4 grid load serves both pixels, 8 independent 128B corner gathers
// in flight per thread. Runs at the measured LTS achievable cap (~6300 B/cyc:
// 1.36GB L2 traffic / 112.7us = 12.1 TB/s). Ten binned/tiled variants that cut
// gather traffic 4x (R3-R15) never beat it — their DRAM-utilization ceiling
// (~56%) consumed the traffic savings.

#define B_ 8
#define H_ 512
#define W_ 512
#define C_ 32
#define NPIX (B_ * H_ * W_)          // 2,097,152
#define NPAIR (NPIX / 2)             // 1,048,576
#define NTHREADS (NPAIR * 8)         // 8,388,608

__device__ __forceinline__ void pixel_setup(
    float gx, float gy, int bbase, int cb,
    unsigned& oa, unsigned& ob, unsigned& oc, unsigned& od,
    float& wa, float& wb, float& wc, float& wd)
{
    // unnormalize: 0.5*((g+1)*511) = g*255.5 + 255.5
    float x = fmaf(gx, 255.5f, 255.5f);
    float y = fmaf(gy, 255.5f, 255.5f);

    float xf = floorf(x);
    float yf = floorf(y);
    int x0 = (int)xf;
    int y0 = (int)yf;

    int x0c = min(max(x0, 0), W_ - 1);
    int x1c = min(max(x0 + 1, 0), W_ - 1);
    int y0c = min(max(y0, 0), H_ - 1);
    int y1c = min(max(y0 + 1, 0), H_ - 1);

    float dx0 = (float)x0c, dx1 = (float)x1c;
    float dy0 = (float)y0c, dy1 = (float)y1c;

    wa = (dx1 - x) * (dy1 - y);
    wb = (dx1 - x) * (y - dy0);
    wc = (x - dx0) * (dy1 - y);
    wd = (x - dx0) * (y - dy0);

    // byte offsets into img (max 2^28-1, fits unsigned)
    unsigned r0 = (unsigned)(bbase + (y0c << 9));   // row base in pixels
    unsigned r1 = (unsigned)(bbase + (y1c << 9));
    oa = ((((r0 + x0c) << 3) + cb) << 4);
    ob = ((((r1 + x0c) << 3) + cb) << 4);
    oc = ((((r0 + x1c) << 3) + cb) << 4);
    od = ((((r1 + x1c) << 3) + cb) << 4);
}

__global__ __launch_bounds__(128, 9)
void grid_sample_kernel(const char* __restrict__ img_bytes,
                        const float4* __restrict__ grid4,
                        float4* __restrict__ out4)
{
    int gtid = blockIdx.x * 128 + threadIdx.x;
    int pair = gtid >> 3;
    int cb   = gtid & 7;
    int pix0 = pair << 1;              // even pixel; pairs never straddle a batch
    int bbase = (pix0 >> 18) << 18;    // b * H * W

    float4 g = __ldg(&grid4[pair]);    // (x0, y0, x1, y1) for pixels pix0, pix0+1

    unsigned oa0, ob0, oc0, od0, oa1, ob1, oc1, od1;
    float wa0, wb0, wc0, wd0, wa1, wb1, wc1, wd1;
    pixel_setup(g.x, g.y, bbase, cb, oa0, ob0, oc0, od0, wa0, wb0, wc0, wd0);
    pixel_setup(g.z, g.w, bbase, cb, oa1, ob1, oc1, od1, wa1, wb1, wc1, wd1);

    // Issue all 8 gathers before consuming any (MLP = 8 per thread).
    float4 Ia0 = __ldg((const float4*)(img_bytes + oa0));
    float4 Ib0 = __ldg((const float4*)(img_bytes + ob0));
    float4 Ic0 = __ldg((const float4*)(img_bytes + oc0));
    float4 Id0 = __ldg((const float4*)(img_bytes + od0));
    float4 Ia1 = __ldg((const float4*)(img_bytes + oa1));
    float4 Ib1 = __ldg((const float4*)(img_bytes + ob1));
    float4 Ic1 = __ldg((const float4*)(img_bytes + oc1));
    float4 Id1 = __ldg((const float4*)(img_bytes + od1));

    float4 o0;
    o0.x = fmaf(wa0, Ia0.x, fmaf(wb0, Ib0.x, fmaf(wc0, Ic0.x, wd0 * Id0.x)));
    o0.y = fmaf(wa0, Ia0.y, fmaf(wb0, Ib0.y, fmaf(wc0, Ic0.y, wd0 * Id0.y)));
    o0.z = fmaf(wa0, Ia0.z, fmaf(wb0, Ib0.z, fmaf(wc0, Ic0.z, wd0 * Id0.z)));
    o0.w = fmaf(wa0, Ia0.w, fmaf(wb0, Ib0.w, fmaf(wc0, Ic0.w, wd0 * Id0.w)));
    __stcs(&out4[((long)pix0 << 3) + cb], o0);

    float4 o1;
    o1.x = fmaf(wa1, Ia1.x, fmaf(wb1, Ib1.x, fmaf(wc1, Ic1.x, wd1 * Id1.x)));
    o1.y = fmaf(wa1, Ia1.y, fmaf(wb1, Ib1.y, fmaf(wc1, Ic1.y, wd1 * Id1.y)));
    o1.z = fmaf(wa1, Ia1.z, fmaf(wb1, Ib1.z, fmaf(wc1, Ic1.z, wd1 * Id1.z)));
    o1.w = fmaf(wa1, Ia1.w, fmaf(wb1, Ib1.w, fmaf(wc1, Ic1.w, wd1 * Id1.w)));
    __stcs(&out4[(((long)pix0 + 1) << 3) + cb], o1);
}

extern "C" void kernel_launch(void* const* d_in, const int* in_sizes, int n_in,
                              void* d_out, int out_size)
{
    const char*   img_bytes = (const char*)d_in[0];
    const float4* grid4     = (const float4*)d_in[1];
    float4* out4 = (float4*)d_out;

    const int threads = 128;
    const int blocks = NTHREADS / threads;  // 65536, exact
    grid_sample_kernel<<<blocks, threads>>>(img_bytes, grid4, out4);
}